// round 10
// baseline (speedup 1.0000x reference)
#include <cuda_runtime.h>

typedef unsigned long long u64;
typedef unsigned int u32;
typedef unsigned short u16;

#define NPG 50
#define EPG 400
#define NGRAPH 32768
#define NEDGE (NGRAPH*EPG)
#define WPC 8                 // warps per CTA in gcn
#define GPW 8                 // graphs per warp
#define T1 (WPC*32)
#define NB 13                 // edge batches of 32 (12*32+16 = 400)
#define PITCH16 56            // u16 cells per tag row (112B: conflict-free LDS.128)
#define BN_EPS 1e-5f

#define FMA2(acc,a,b) asm("fma.rn.f32x2 %0,%1,%2,%0;" : "+l"(acc) : "l"(a), "l"(b))
#define ADD2(acc,a)   asm("add.rn.f32x2 %0,%1,%0;"    : "+l"(acc) : "l"(a))
__device__ __forceinline__ u64 packf2(float lo, float hi) {
    u64 r; asm("mov.b64 %0,{%1,%2};" : "=l"(r) : "r"(__float_as_uint(lo)), "r"(__float_as_uint(hi)));
    return r;
}
__device__ __forceinline__ float lo32(u64 v){ return __uint_as_float((unsigned)v); }
__device__ __forceinline__ float hi32(u64 v){ return __uint_as_float((unsigned)(v>>32)); }

// ---------------- device scratch (static; no allocation) ----------------
__device__ u64   g_GGc[NPG*16];    // interleaved (G, Gc) folded fc1 weights
__device__ float g_e1[16];
__device__ float g_sum1[16], g_ss1[16];
__device__ float g_sum2[32], g_ss2[32];
__device__ float g_a1[NGRAPH*16];  // 2 MB
__device__ float g_a2[NGRAPH*32];  // 4 MB

// ---------------- prep: fold W1k@W2k into fc1, zero accumulators ----------------
__global__ void prep_kernel(const float* __restrict__ W11, const float* __restrict__ b11,
                            const float* __restrict__ W21, const float* __restrict__ b21,
                            const float* __restrict__ W12, const float* __restrict__ b12,
                            const float* __restrict__ W22, const float* __restrict__ b22,
                            const float* __restrict__ W13, const float* __restrict__ b13,
                            const float* __restrict__ W23, const float* __restrict__ b23,
                            const float* __restrict__ fc1w, const float* __restrict__ fc1b)
{
    __shared__ float u[12], cv[12], dv[12];
    int tid = threadIdx.x;
    if (tid < 12) {
        int k = tid / 4, o = tid % 4;
        const float* W1 = (k==0) ? W11 : ((k==1) ? W12 : W13);
        const float* W2 = (k==0) ? W21 : ((k==1) ? W22 : W23);
        const float* b1 = (k==0) ? b11 : ((k==1) ? b12 : b13);
        const float* b2 = (k==0) ? b21 : ((k==1) ? b22 : b23);
        float uu = 0.f, cc = 0.f;
        #pragma unroll
        for (int m = 0; m < 4; ++m) { uu += W1[m]*W2[m*4+o]; cc += b1[m]*W2[m*4+o]; }
        u[tid] = uu; cv[tid] = cc; dv[tid] = b2[o];
    }
    __syncthreads();
    for (int i = tid; i < NPG*16; i += blockDim.x) {
        int j = i >> 4, o = i & 15;
        float gg = 0.f, gc = 0.f;
        #pragma unroll
        for (int f = 0; f < 12; ++f) {
            float w = fc1w[(j*12+f)*16 + o];
            gg += u[f]*w; gc += cv[f]*w;
        }
        g_GGc[i] = packf2(gg, gc);
    }
    if (tid < 16) {
        float e = fc1b[tid];
        for (int j = 0; j < NPG; ++j)
            #pragma unroll
            for (int f = 0; f < 12; ++f)
                e += dv[f]*fc1w[(j*12+f)*16 + tid];
        g_e1[tid] = e;
        g_sum1[tid] = 0.f; g_ss1[tid] = 0.f;
    }
    if (tid < 32) { g_sum2[tid] = 0.f; g_ss2[tid] = 0.f; }
}

// ---- scan one tag row -> 50-bit structure mask (m0: cells 0..31, m1: 32..49) ----
// cell valid iff tag epoch byte matches: ((tag>>8) ^ (gi<<1)) & 0xFE == 0
__device__ __forceinline__ void scan_row_tags(const u16* __restrict__ tag, int r, u32 ep2,
                                              u32& m0, u32& m1)
{
    const uint4* row4 = (const uint4*)(tag + r*PITCH16);
    m0 = 0; m1 = 0;
    #pragma unroll
    for (int k4 = 0; k4 < 7; ++k4) {
        uint4 q = row4[k4];
        u32 p0 = __byte_perm(q.x, q.y, 0x7531);    // hi-bytes of 4 u16 cells
        u32 p1 = __byte_perm(q.z, q.w, 0x7531);
        u32 v0 = (p0 ^ ep2) & 0xFEFEFEFEu;
        u32 v1 = (p1 ^ ep2) & 0xFEFEFEFEu;
        u32 f0 = __vseteq4(v0, 0u);                // 0x01 per valid cell
        u32 f1 = __vseteq4(v1, 0u);
        u32 nib = ((f0 * 0x01020408u) >> 24) | ((((f1 * 0x01020408u) >> 24)) << 4);
        if (k4 < 4) m0 |= nib << (8*k4); else m1 |= nib << (8*(k4-4));
    }
}

// ---- packed sweep: ident + structure bits + dup bits (each dup cell counted twice total) ----
__device__ __forceinline__ u64 sweep1p(u32 m0, u32 m1, u32 dl, u32 dh,
                                       const u64* __restrict__ wv, u64 acc)
{
    while (m0) { int j = __ffs(m0)-1;  m0 &= m0-1; u64 v = wv[j]; ADD2(acc, v); }
    while (m1) { int j = __ffs(m1)+31; m1 &= m1-1; u64 v = wv[j]; ADD2(acc, v); }
    while (dl) { int j = __ffs(dl)-1;  dl &= dl-1; u64 v = wv[j]; ADD2(acc, v); }
    while (dh) { int j = __ffs(dh)+31; dh &= dh-1; u64 v = wv[j]; ADD2(acc, v); }
    return acc;
}
__device__ __forceinline__ float sweep2s(u32 m0, u32 m1, u32 dl, u32 dh,
                                         const float* __restrict__ wv, float acc)
{
    while (m0) { int j = __ffs(m0)-1;  m0 &= m0-1; acc += wv[j]; }
    while (m1) { int j = __ffs(m1)+31; m1 &= m1-1; acc += wv[j]; }
    while (dl) { int j = __ffs(dl)-1;  dl &= dl-1; acc += wv[j]; }
    while (dh) { int j = __ffs(dh)+31; dh &= dh-1; acc += wv[j]; }
    return acc;
}

// ---------------- main GCN kernel: warp-per-graph, tag-dedup build (STS not atomics) ----------------
__global__ void __launch_bounds__(T1, 3) gcn_kernel(const float* __restrict__ x,
                                                    const int* __restrict__ ei)
{
    __shared__ __align__(16) u16 sTag[WPC][NPG*PITCH16];  // 5.6KB/warp last-writer tags
    __shared__ u64   sWxd[WPC][NPG];
    __shared__ float sW2[WPC][NPG];
    __shared__ u64   sYR[WPC][NPG];
    __shared__ u64   sDm[WPC][NPG];                        // dup masks (count>=2 cells)
    __shared__ u16   sTrl[WPC][64];                        // triple+ list (rare)
    __shared__ int   sNtr[WPC];
    __shared__ u64   sGGc[NPG*16];
    __shared__ float se1[16];

    int tid = threadIdx.x, w = tid >> 5, lane = tid & 31;
    // once per launch: invalidate all tags (0xFFFF never matches any epoch)
    {
        u32* tp = (u32*)sTag;
        for (int i = tid; i < WPC*NPG*PITCH16/2; i += T1) tp[i] = 0xFFFFFFFFu;
    }
    for (int i = tid; i < NPG*16; i += T1) sGGc[i] = g_GGc[i];
    if (tid < 16) se1[tid] = g_e1[tid];
    __syncthreads();

    u16*  tag = sTag[w];
    u64*  wxd = sWxd[w];
    float* w2 = sW2[w];
    u64*  yr  = sYR[w];
    u64*  dm  = sDm[w];
    u16*  trl = sTrl[w];

    const int r1 = lane, r2 = 32 + lane;
    const bool has2 = (lane < NPG - 32);
    float psum = 0.f, pss = 0.f;
    int gbase = (blockIdx.x * WPC + w) * GPW;

    int eS[NB], eD[NB]; float px1, px2;
    {   // prologue: first graph's edges + x
        int eb = gbase*EPG, nb0 = gbase*NPG;
        #pragma unroll
        for (int b = 0; b < NB; ++b) {
            bool act = (b < 12) || (lane < 16);
            int e = lane + b*32;
            eS[b] = act ? ei[eb+e] : nb0;
            eD[b] = act ? ei[NEDGE+eb+e] : nb0;
        }
        px1 = x[nb0 + r1];
        px2 = has2 ? x[nb0 + r2] : 0.f;
    }

    for (int gi = 0; gi < GPW; ++gi) {
        int g = gbase + gi, nb = g*NPG;
        float x1 = px1, x2 = px2;
        // Z: zero dup masks + triple count
        dm[r1] = 0ull;
        if (has2) dm[r2] = 0ull;
        if (lane == 0) sNtr[w] = 0;
        __syncwarp();
        // T: last-writer tag write (plain STS; races pick one winner)
        u32 epv = (u32)gi << 9;
        #pragma unroll
        for (int b = 0; b < NB; ++b) {
            bool act = (b < 12) || (lane < 16);
            if (act) {
                int s = eS[b]-nb, d = eD[b]-nb;
                tag[d*PITCH16 + s] = (u16)(epv | (u32)(b*32 + lane));
            }
        }
        __syncwarp();
        // R: read back -> non-owners are duplicates; set dup-mask bit; triples to list
        #pragma unroll
        for (int b = 0; b < NB; ++b) {
            bool act = (b < 12) || (lane < 16);
            if (act) {
                int s = eS[b]-nb, d = eD[b]-nb;
                u16 t = tag[d*PITCH16 + s];
                if (t != (u16)(epv | (u32)(b*32 + lane))) {
                    u64 bit = 1ull << s;
                    u64 old = atomicOr(&dm[d], bit);
                    if (old & bit) {
                        int k = atomicAdd(&sNtr[w], 1);
                        if (k < 64) trl[k] = (u16)(d*64 + s);
                    }
                }
            }
        }
        // prefetch next graph's edges + x
        if (gi + 1 < GPW) {
            int eb2 = (g+1)*EPG, nb2 = (g+1)*NPG;
            #pragma unroll
            for (int b = 0; b < NB; ++b) {
                bool act = (b < 12) || (lane < 16);
                int e = lane + b*32;
                if (act) { eS[b] = ei[eb2+e]; eD[b] = ei[NEDGE+eb2+e]; }
                else     { eS[b] = nb2; eD[b] = nb2; }
            }
            px1 = x[nb2 + r1];
            px2 = has2 ? x[nb2 + r2] : 0.f;
        }
        __syncwarp();
        // S: scan tags -> register structure masks; degree; wxd
        int ntr = sNtr[w];
        u64 dv1 = dm[r1], dv2 = has2 ? dm[r2] : 0ull;
        u32 ep2 = ((u32)gi << 1) * 0x01010101u;
        u32 m0a, m1a, m0b = 0, m1b = 0;
        scan_row_tags(tag, r1, ep2, m0a, m1a);
        if (has2) scan_row_tags(tag, r2, ep2, m0b, m1b);
        float degA = 1.f + (float)(__popc(m0a) + __popc(m1a) + __popcll(dv1));
        float degB = 1.f + (float)(__popc(m0b) + __popc(m1b) + __popcll(dv2));
        if (ntr) {
            for (int k = 0; k < ntr && k < 64; ++k) {
                int c = trl[k], d = c >> 6;
                if (d == r1) degA += 1.f;
                if (has2 && d == r2) degB += 1.f;
            }
        }
        float di1 = rsqrtf(degA), di2 = rsqrtf(degB);
        u64 idA = packf2(x1*di1, di1);
        wxd[r1] = idA;
        u64 idB = 0;
        if (has2) { idB = packf2(x2*di2, di2); wxd[r2] = idB; }
        __syncwarp();
        // sweep 1 (x-path + ones-path packed f32x2)
        u64 acca = sweep1p(m0a, m1a, (u32)dv1, (u32)(dv1>>32), wxd, idA);
        u64 accb = has2 ? sweep1p(m0b, m1b, (u32)dv2, (u32)(dv2>>32), wxd, idB) : 0ull;
        if (ntr) {
            for (int k = 0; k < ntr && k < 64; ++k) {
                int c = trl[k], d = c >> 6, s = c & 63;
                if (d == r1)          { u64 v = wxd[s]; ADD2(acca, v); }
                if (has2 && d == r2)  { u64 v = wxd[s]; ADD2(accb, v); }
            }
        }
        float rv1 = hi32(acca)*di1;
        float w2a = lo32(acca)*di1*di1;
        w2[r1] = w2a;
        float rv2 = 0.f, w2b = 0.f;
        if (has2) { rv2 = hi32(accb)*di2; w2b = lo32(accb)*di2*di2; w2[r2] = w2b; }
        __syncwarp();
        // sweep 2 (scalar)
        float a2v = sweep2s(m0a, m1a, (u32)dv1, (u32)(dv1>>32), w2, w2a);
        float b2v = has2 ? sweep2s(m0b, m1b, (u32)dv2, (u32)(dv2>>32), w2, w2b) : 0.f;
        if (ntr) {
            for (int k = 0; k < ntr && k < 64; ++k) {
                int c = trl[k], d = c >> 6, s = c & 63;
                if (d == r1)         a2v += w2[s];
                if (has2 && d == r2) b2v += w2[s];
            }
        }
        yr[r1] = packf2(a2v*di1, rv1);
        if (has2) yr[r2] = packf2(b2v*di2, rv2);
        __syncwarp();
        // fc1: a1[g,o] = e1[o] + sum_j yv[j]G[j,o] + rv[j]Gc[j,o]
        {
            int o = lane & 15, half = lane >> 4;
            int j0 = half * 25;
            u64 acc = 0;
            #pragma unroll
            for (int j = 0; j < 25; ++j) {
                u64 y  = yr[j0 + j];
                u64 gg = sGGc[(j0 + j)*16 + o];
                FMA2(acc, y, gg);
            }
            float s = lo32(acc) + hi32(acc);
            s += __shfl_down_sync(0xffffffffu, s, 16);
            if (lane < 16) {
                float a = fmaxf(se1[o] + s, 0.f);
                g_a1[g*16 + o] = a;
                psum += a; pss += a*a;
            }
        }
        __syncwarp();
    }
    if (lane < 16) { atomicAdd(&g_sum1[lane], psum); atomicAdd(&g_ss1[lane], pss); }
}

// ---------------- fc2: BN1 fold + GEMV + relu -> g_a2 + BN2 stats (transpose tile) ----------------
__global__ void __launch_bounds__(128) fc2_kernel(const float* __restrict__ fc2w,
                                                  const float* __restrict__ fc2b,
                                                  const float* __restrict__ g1,
                                                  const float* __restrict__ bb1)
{
    __shared__ float sS[16], sOff[16];
    __shared__ float4 sW4[16*8];
    __shared__ float sc2[32];
    __shared__ float tile[4][32][33];
    __shared__ float rsum[32], rss[32];
    int tid = threadIdx.x, lane = tid & 31, w = tid >> 5;
    if (tid < 16) {
        float m = g_sum1[tid] * (1.0f/NGRAPH);
        float v = g_ss1[tid] * (1.0f/NGRAPH) - m*m;
        float sc = rsqrtf(v + BN_EPS) * g1[tid];
        sS[tid] = sc; sOff[tid] = bb1[tid] - m*sc;
    }
    if (tid < 32) { rsum[tid] = 0.f; rss[tid] = 0.f; }
    __syncthreads();
    float* sW = (float*)sW4;
    for (int i = tid; i < 512; i += 128) sW[i] = sS[i >> 5] * fc2w[i];
    if (tid < 32) {
        float c = fc2b[tid];
        #pragma unroll
        for (int r = 0; r < 16; ++r) c += sOff[r]*fc2w[r*32+tid];
        sc2[tid] = c;
    }
    __syncthreads();

    int b = blockIdx.x*128 + tid;
    const float4* a4 = (const float4*)&g_a1[b*16];
    float4 r0 = a4[0], r1 = a4[1], r2 = a4[2], r3 = a4[3];
    float a[16] = {r0.x,r0.y,r0.z,r0.w, r1.x,r1.y,r1.z,r1.w,
                   r2.x,r2.y,r2.z,r2.w, r3.x,r3.y,r3.z,r3.w};
    float4* out4 = (float4*)&g_a2[b*32];
    #pragma unroll
    for (int o4 = 0; o4 < 8; ++o4) {
        float4 acc = make_float4(sc2[o4*4], sc2[o4*4+1], sc2[o4*4+2], sc2[o4*4+3]);
        #pragma unroll
        for (int i = 0; i < 16; ++i) {
            float4 ww = sW4[i*8 + o4];
            acc.x += a[i]*ww.x; acc.y += a[i]*ww.y; acc.z += a[i]*ww.z; acc.w += a[i]*ww.w;
        }
        acc.x = fmaxf(acc.x, 0.f); acc.y = fmaxf(acc.y, 0.f);
        acc.z = fmaxf(acc.z, 0.f); acc.w = fmaxf(acc.w, 0.f);
        out4[o4] = acc;
        tile[w][lane][o4*4]   = acc.x; tile[w][lane][o4*4+1] = acc.y;
        tile[w][lane][o4*4+2] = acc.z; tile[w][lane][o4*4+3] = acc.w;
    }
    __syncwarp();
    float s = 0.f, ss = 0.f;
    #pragma unroll
    for (int j = 0; j < 32; ++j) {
        float v = tile[w][j][lane];
        s += v; ss += v*v;
    }
    atomicAdd(&rsum[lane], s);
    atomicAdd(&rss[lane], ss);
    __syncthreads();
    if (tid < 32) { atomicAdd(&g_sum2[tid], rsum[tid]); atomicAdd(&g_ss2[tid], rss[tid]); }
}

// ---------------- fc3: in-block BN2 fold + final logits (reads g_a2) ----------------
__global__ void __launch_bounds__(128) fc3_kernel(float* __restrict__ out,
                                                  const float* __restrict__ fc3w,
                                                  const float* __restrict__ fc3b,
                                                  const float* __restrict__ g2,
                                                  const float* __restrict__ bb2)
{
    __shared__ float sS[32], sOff[32], sW[64], sc3[2];
    int tid = threadIdx.x;
    if (tid < 32) {
        float m = g_sum2[tid] * (1.0f/NGRAPH);
        float v = g_ss2[tid] * (1.0f/NGRAPH) - m*m;
        float sc = rsqrtf(v + BN_EPS) * g2[tid];
        sS[tid] = sc; sOff[tid] = bb2[tid] - m*sc;
    }
    __syncthreads();
    if (tid < 64) sW[tid] = sS[tid >> 1] * fc3w[tid];
    if (tid < 2) {
        float c = fc3b[tid];
        #pragma unroll
        for (int r = 0; r < 32; ++r) c += sOff[r]*fc3w[r*2+tid];
        sc3[tid] = c;
    }
    __syncthreads();
    int b = blockIdx.x*128 + tid;
    const float4* a2r = (const float4*)&g_a2[b*32];
    float o0 = sc3[0], o1 = sc3[1];
    #pragma unroll
    for (int q = 0; q < 8; ++q) {
        float4 v = a2r[q];
        o0 += v.x*sW[(q*4+0)*2]   + v.y*sW[(q*4+1)*2]   + v.z*sW[(q*4+2)*2]   + v.w*sW[(q*4+3)*2];
        o1 += v.x*sW[(q*4+0)*2+1] + v.y*sW[(q*4+1)*2+1] + v.z*sW[(q*4+2)*2+1] + v.w*sW[(q*4+3)*2+1];
    }
    ((float2*)out)[b] = make_float2(o0, o1);
}

// ---------------- launch ----------------
extern "C" void kernel_launch(void* const* d_in, const int* in_sizes, int n_in,
                              void* d_out, int out_size)
{
    const float* x    = (const float*)d_in[0];
    const int*   ei   = (const int*)  d_in[1];
    const float* W11  = (const float*)d_in[2];
    const float* b11  = (const float*)d_in[3];
    const float* W21  = (const float*)d_in[4];
    const float* b21  = (const float*)d_in[5];
    const float* W12  = (const float*)d_in[6];
    const float* b12  = (const float*)d_in[7];
    const float* W22  = (const float*)d_in[8];
    const float* b22  = (const float*)d_in[9];
    const float* W13  = (const float*)d_in[10];
    const float* b13  = (const float*)d_in[11];
    const float* W23  = (const float*)d_in[12];
    const float* b23  = (const float*)d_in[13];
    const float* fc1w = (const float*)d_in[14];
    const float* fc1b = (const float*)d_in[15];
    const float* bn1g = (const float*)d_in[16];
    const float* bn1b = (const float*)d_in[17];
    const float* fc2w = (const float*)d_in[18];
    const float* fc2b = (const float*)d_in[19];
    const float* bn2g = (const float*)d_in[20];
    const float* bn2b = (const float*)d_in[21];
    const float* fc3w = (const float*)d_in[22];
    const float* fc3b = (const float*)d_in[23];

    prep_kernel<<<1, 256>>>(W11,b11,W21,b21,W12,b12,W22,b22,W13,b13,W23,b23,fc1w,fc1b);
    gcn_kernel<<<NGRAPH/(WPC*GPW), T1>>>(x, ei);
    fc2_kernel<<<NGRAPH/128, 128>>>(fc2w, fc2b, bn1g, bn1b);
    fc3_kernel<<<NGRAPH/128, 128>>>((float*)d_out, fc3w, fc3b, bn2g, bn2b);
}

// round 11
// speedup vs baseline: 1.0152x; 1.0152x over previous
#include <cuda_runtime.h>

typedef unsigned long long u64;
typedef unsigned int u32;
typedef unsigned short u16;

#define NPG 50
#define EPG 400
#define NGRAPH 32768
#define NEDGE (NGRAPH*EPG)
#define WPC 8                 // warps per CTA in gcn
#define GPW 8                 // graphs per warp
#define T1 (WPC*32)
#define NB 13                 // edge batches of 32 (12*32+16 = 400)
#define PITCH16 56            // u16 cells per tag row (112B: conflict-free LDS.128)
#define BN_EPS 1e-5f

#define FMA2(acc,a,b) asm("fma.rn.f32x2 %0,%1,%2,%0;" : "+l"(acc) : "l"(a), "l"(b))
#define ADD2(acc,a)   asm("add.rn.f32x2 %0,%1,%0;"    : "+l"(acc) : "l"(a))
__device__ __forceinline__ u64 packf2(float lo, float hi) {
    u64 r; asm("mov.b64 %0,{%1,%2};" : "=l"(r) : "r"(__float_as_uint(lo)), "r"(__float_as_uint(hi)));
    return r;
}
__device__ __forceinline__ float lo32(u64 v){ return __uint_as_float((unsigned)v); }
__device__ __forceinline__ float hi32(u64 v){ return __uint_as_float((unsigned)(v>>32)); }

// ---------------- device scratch (static; no allocation) ----------------
__device__ u64   g_GGc[NPG*16];    // interleaved (G, Gc) folded fc1 weights
__device__ float g_e1[16];
__device__ float g_sum1[16], g_ss1[16];
__device__ float g_sum2[32], g_ss2[32];
__device__ float g_a1[NGRAPH*16];  // 2 MB
__device__ float g_a2[NGRAPH*32];  // 4 MB

// ---------------- prep: fold W1k@W2k into fc1, zero accumulators ----------------
__global__ void prep_kernel(const float* __restrict__ W11, const float* __restrict__ b11,
                            const float* __restrict__ W21, const float* __restrict__ b21,
                            const float* __restrict__ W12, const float* __restrict__ b12,
                            const float* __restrict__ W22, const float* __restrict__ b22,
                            const float* __restrict__ W13, const float* __restrict__ b13,
                            const float* __restrict__ W23, const float* __restrict__ b23,
                            const float* __restrict__ fc1w, const float* __restrict__ fc1b)
{
    __shared__ float u[12], cv[12], dv[12];
    int tid = threadIdx.x;
    if (tid < 12) {
        int k = tid / 4, o = tid % 4;
        const float* W1 = (k==0) ? W11 : ((k==1) ? W12 : W13);
        const float* W2 = (k==0) ? W21 : ((k==1) ? W22 : W23);
        const float* b1 = (k==0) ? b11 : ((k==1) ? b12 : b13);
        const float* b2 = (k==0) ? b21 : ((k==1) ? b22 : b23);
        float uu = 0.f, cc = 0.f;
        #pragma unroll
        for (int m = 0; m < 4; ++m) { uu += W1[m]*W2[m*4+o]; cc += b1[m]*W2[m*4+o]; }
        u[tid] = uu; cv[tid] = cc; dv[tid] = b2[o];
    }
    __syncthreads();
    for (int i = tid; i < NPG*16; i += blockDim.x) {
        int j = i >> 4, o = i & 15;
        float gg = 0.f, gc = 0.f;
        #pragma unroll
        for (int f = 0; f < 12; ++f) {
            float w = fc1w[(j*12+f)*16 + o];
            gg += u[f]*w; gc += cv[f]*w;
        }
        g_GGc[i] = packf2(gg, gc);
    }
    if (tid < 16) {
        float e = fc1b[tid];
        for (int j = 0; j < NPG; ++j)
            #pragma unroll
            for (int f = 0; f < 12; ++f)
                e += dv[f]*fc1w[(j*12+f)*16 + tid];
        g_e1[tid] = e;
        g_sum1[tid] = 0.f; g_ss1[tid] = 0.f;
    }
    if (tid < 32) { g_sum2[tid] = 0.f; g_ss2[tid] = 0.f; }
}

// ---- scan one tag row -> 50-bit structure mask (m0: cells 0..31, m1: 32..49) ----
// cell valid iff tag epoch byte matches: ((tag>>8) ^ (gi<<1)) & 0xFE == 0
__device__ __forceinline__ void scan_row_tags(const u16* __restrict__ tag, int r, u32 ep2,
                                              u32& m0, u32& m1)
{
    const uint4* row4 = (const uint4*)(tag + r*PITCH16);
    m0 = 0; m1 = 0;
    #pragma unroll
    for (int k4 = 0; k4 < 7; ++k4) {
        uint4 q = row4[k4];
        u32 p0 = __byte_perm(q.x, q.y, 0x7531);    // hi-bytes of 4 u16 cells
        u32 p1 = __byte_perm(q.z, q.w, 0x7531);
        u32 v0 = (p0 ^ ep2) & 0xFEFEFEFEu;
        u32 v1 = (p1 ^ ep2) & 0xFEFEFEFEu;
        u32 f0 = __vseteq4(v0, 0u);                // 0x01 per valid cell
        u32 f1 = __vseteq4(v1, 0u);
        u32 nib = ((f0 * 0x01020408u) >> 24) | ((((f1 * 0x01020408u) >> 24)) << 4);
        if (k4 < 4) m0 |= nib << (8*k4); else m1 |= nib << (8*(k4-4));
    }
}

// ---- packed sweep: ident + structure bits + dup bits (each dup cell counted twice total) ----
__device__ __forceinline__ u64 sweep1p(u32 m0, u32 m1, u32 dl, u32 dh,
                                       const u64* __restrict__ wv, u64 acc)
{
    while (m0) { int j = __ffs(m0)-1;  m0 &= m0-1; u64 v = wv[j]; ADD2(acc, v); }
    while (m1) { int j = __ffs(m1)+31; m1 &= m1-1; u64 v = wv[j]; ADD2(acc, v); }
    while (dl) { int j = __ffs(dl)-1;  dl &= dl-1; u64 v = wv[j]; ADD2(acc, v); }
    while (dh) { int j = __ffs(dh)+31; dh &= dh-1; u64 v = wv[j]; ADD2(acc, v); }
    return acc;
}
__device__ __forceinline__ float sweep2s(u32 m0, u32 m1, u32 dl, u32 dh,
                                         const float* __restrict__ wv, float acc)
{
    while (m0) { int j = __ffs(m0)-1;  m0 &= m0-1; acc += wv[j]; }
    while (m1) { int j = __ffs(m1)+31; m1 &= m1-1; acc += wv[j]; }
    while (dl) { int j = __ffs(dl)-1;  dl &= dl-1; acc += wv[j]; }
    while (dh) { int j = __ffs(dh)+31; dh &= dh-1; acc += wv[j]; }
    return acc;
}

// ---------------- main GCN kernel: warp-per-graph, tag-dedup build (STS not atomics) ----------------
__global__ void __launch_bounds__(T1, 3) gcn_kernel(const float* __restrict__ x,
                                                    const int* __restrict__ ei)
{
    __shared__ __align__(16) u16 sTag[WPC][NPG*PITCH16];  // 5.6KB/warp last-writer tags
    __shared__ u64   sWxd[WPC][NPG];
    __shared__ float sW2[WPC][NPG];
    __shared__ u64   sYR[WPC][NPG];
    __shared__ u64   sDm[WPC][NPG];                        // dup masks (count>=2 cells)
    __shared__ u16   sTrl[WPC][64];                        // triple+ list (rare)
    __shared__ int   sNtr[WPC];
    __shared__ u64   sGGc[NPG*16];
    __shared__ float se1[16];

    int tid = threadIdx.x, w = tid >> 5, lane = tid & 31;
    // once per launch: invalidate all tags (0xFFFF never matches any epoch)
    {
        u32* tp = (u32*)sTag;
        for (int i = tid; i < WPC*NPG*PITCH16/2; i += T1) tp[i] = 0xFFFFFFFFu;
    }
    for (int i = tid; i < NPG*16; i += T1) sGGc[i] = g_GGc[i];
    if (tid < 16) se1[tid] = g_e1[tid];
    __syncthreads();

    u16*  tag = sTag[w];
    u64*  wxd = sWxd[w];
    float* w2 = sW2[w];
    u64*  yr  = sYR[w];
    u64*  dm  = sDm[w];
    u16*  trl = sTrl[w];

    const int r1 = lane, r2 = 32 + lane;
    const bool has2 = (lane < NPG - 32);
    float psum = 0.f, pss = 0.f;
    int gbase = (blockIdx.x * WPC + w) * GPW;

    int eS[NB], eD[NB]; float px1, px2;
    {   // prologue: first graph's edges + x
        int eb = gbase*EPG, nb0 = gbase*NPG;
        #pragma unroll
        for (int b = 0; b < NB; ++b) {
            bool act = (b < 12) || (lane < 16);
            int e = lane + b*32;
            eS[b] = act ? ei[eb+e] : nb0;
            eD[b] = act ? ei[NEDGE+eb+e] : nb0;
        }
        px1 = x[nb0 + r1];
        px2 = has2 ? x[nb0 + r2] : 0.f;
    }

    for (int gi = 0; gi < GPW; ++gi) {
        int g = gbase + gi, nb = g*NPG;
        float x1 = px1, x2 = px2;
        // Z: zero dup masks + triple count
        dm[r1] = 0ull;
        if (has2) dm[r2] = 0ull;
        if (lane == 0) sNtr[w] = 0;
        __syncwarp();
        // T: last-writer tag write (plain STS; races pick one winner)
        u32 epv = (u32)gi << 9;
        #pragma unroll
        for (int b = 0; b < NB; ++b) {
            bool act = (b < 12) || (lane < 16);
            if (act) {
                int s = eS[b]-nb, d = eD[b]-nb;
                tag[d*PITCH16 + s] = (u16)(epv | (u32)(b*32 + lane));
            }
        }
        __syncwarp();
        // R: read back -> non-owners are duplicates; set dup-mask bit; triples to list
        #pragma unroll
        for (int b = 0; b < NB; ++b) {
            bool act = (b < 12) || (lane < 16);
            if (act) {
                int s = eS[b]-nb, d = eD[b]-nb;
                u16 t = tag[d*PITCH16 + s];
                if (t != (u16)(epv | (u32)(b*32 + lane))) {
                    u64 bit = 1ull << s;
                    u64 old = atomicOr(&dm[d], bit);
                    if (old & bit) {
                        int k = atomicAdd(&sNtr[w], 1);
                        if (k < 64) trl[k] = (u16)(d*64 + s);
                    }
                }
            }
        }
        // prefetch next graph's edges + x
        if (gi + 1 < GPW) {
            int eb2 = (g+1)*EPG, nb2 = (g+1)*NPG;
            #pragma unroll
            for (int b = 0; b < NB; ++b) {
                bool act = (b < 12) || (lane < 16);
                int e = lane + b*32;
                if (act) { eS[b] = ei[eb2+e]; eD[b] = ei[NEDGE+eb2+e]; }
                else     { eS[b] = nb2; eD[b] = nb2; }
            }
            px1 = x[nb2 + r1];
            px2 = has2 ? x[nb2 + r2] : 0.f;
        }
        __syncwarp();
        // S: scan tags -> register structure masks; degree; wxd
        int ntr = sNtr[w];
        u64 dv1 = dm[r1], dv2 = has2 ? dm[r2] : 0ull;
        u32 ep2 = ((u32)gi << 1) * 0x01010101u;
        u32 m0a, m1a, m0b = 0, m1b = 0;
        scan_row_tags(tag, r1, ep2, m0a, m1a);
        if (has2) scan_row_tags(tag, r2, ep2, m0b, m1b);
        float degA = 1.f + (float)(__popc(m0a) + __popc(m1a) + __popcll(dv1));
        float degB = 1.f + (float)(__popc(m0b) + __popc(m1b) + __popcll(dv2));
        if (ntr) {
            for (int k = 0; k < ntr && k < 64; ++k) {
                int c = trl[k], d = c >> 6;
                if (d == r1) degA += 1.f;
                if (has2 && d == r2) degB += 1.f;
            }
        }
        float di1 = rsqrtf(degA), di2 = rsqrtf(degB);
        u64 idA = packf2(x1*di1, di1);
        wxd[r1] = idA;
        u64 idB = 0;
        if (has2) { idB = packf2(x2*di2, di2); wxd[r2] = idB; }
        __syncwarp();
        // sweep 1 (x-path + ones-path packed f32x2)
        u64 acca = sweep1p(m0a, m1a, (u32)dv1, (u32)(dv1>>32), wxd, idA);
        u64 accb = has2 ? sweep1p(m0b, m1b, (u32)dv2, (u32)(dv2>>32), wxd, idB) : 0ull;
        if (ntr) {
            for (int k = 0; k < ntr && k < 64; ++k) {
                int c = trl[k], d = c >> 6, s = c & 63;
                if (d == r1)          { u64 v = wxd[s]; ADD2(acca, v); }
                if (has2 && d == r2)  { u64 v = wxd[s]; ADD2(accb, v); }
            }
        }
        float rv1 = hi32(acca)*di1;
        float w2a = lo32(acca)*di1*di1;
        w2[r1] = w2a;
        float rv2 = 0.f, w2b = 0.f;
        if (has2) { rv2 = hi32(accb)*di2; w2b = lo32(accb)*di2*di2; w2[r2] = w2b; }
        __syncwarp();
        // sweep 2 (scalar)
        float a2v = sweep2s(m0a, m1a, (u32)dv1, (u32)(dv1>>32), w2, w2a);
        float b2v = has2 ? sweep2s(m0b, m1b, (u32)dv2, (u32)(dv2>>32), w2, w2b) : 0.f;
        if (ntr) {
            for (int k = 0; k < ntr && k < 64; ++k) {
                int c = trl[k], d = c >> 6, s = c & 63;
                if (d == r1)         a2v += w2[s];
                if (has2 && d == r2) b2v += w2[s];
            }
        }
        yr[r1] = packf2(a2v*di1, rv1);
        if (has2) yr[r2] = packf2(b2v*di2, rv2);
        __syncwarp();
        // fc1: a1[g,o] = e1[o] + sum_j yv[j]G[j,o] + rv[j]Gc[j,o]
        {
            int o = lane & 15, half = lane >> 4;
            int j0 = half * 25;
            u64 acc = 0;
            #pragma unroll
            for (int j = 0; j < 25; ++j) {
                u64 y  = yr[j0 + j];
                u64 gg = sGGc[(j0 + j)*16 + o];
                FMA2(acc, y, gg);
            }
            float s = lo32(acc) + hi32(acc);
            s += __shfl_down_sync(0xffffffffu, s, 16);
            if (lane < 16) {
                float a = fmaxf(se1[o] + s, 0.f);
                g_a1[g*16 + o] = a;
                psum += a; pss += a*a;
            }
        }
        __syncwarp();
    }
    if (lane < 16) { atomicAdd(&g_sum1[lane], psum); atomicAdd(&g_ss1[lane], pss); }
}

// ---------------- fc2: BN1 fold + GEMV + relu -> g_a2 + BN2 stats (transpose tile) ----------------
__global__ void __launch_bounds__(128) fc2_kernel(const float* __restrict__ fc2w,
                                                  const float* __restrict__ fc2b,
                                                  const float* __restrict__ g1,
                                                  const float* __restrict__ bb1)
{
    __shared__ float sS[16], sOff[16];
    __shared__ float4 sW4[16*8];
    __shared__ float sc2[32];
    __shared__ float tile[4][32][33];
    __shared__ float rsum[32], rss[32];
    int tid = threadIdx.x, lane = tid & 31, w = tid >> 5;
    if (tid < 16) {
        float m = g_sum1[tid] * (1.0f/NGRAPH);
        float v = g_ss1[tid] * (1.0f/NGRAPH) - m*m;
        float sc = rsqrtf(v + BN_EPS) * g1[tid];
        sS[tid] = sc; sOff[tid] = bb1[tid] - m*sc;
    }
    if (tid < 32) { rsum[tid] = 0.f; rss[tid] = 0.f; }
    __syncthreads();
    float* sW = (float*)sW4;
    for (int i = tid; i < 512; i += 128) sW[i] = sS[i >> 5] * fc2w[i];
    if (tid < 32) {
        float c = fc2b[tid];
        #pragma unroll
        for (int r = 0; r < 16; ++r) c += sOff[r]*fc2w[r*32+tid];
        sc2[tid] = c;
    }
    __syncthreads();

    int b = blockIdx.x*128 + tid;
    const float4* a4 = (const float4*)&g_a1[b*16];
    float4 r0 = a4[0], r1 = a4[1], r2 = a4[2], r3 = a4[3];
    float a[16] = {r0.x,r0.y,r0.z,r0.w, r1.x,r1.y,r1.z,r1.w,
                   r2.x,r2.y,r2.z,r2.w, r3.x,r3.y,r3.z,r3.w};
    float4* out4 = (float4*)&g_a2[b*32];
    #pragma unroll
    for (int o4 = 0; o4 < 8; ++o4) {
        float4 acc = make_float4(sc2[o4*4], sc2[o4*4+1], sc2[o4*4+2], sc2[o4*4+3]);
        #pragma unroll
        for (int i = 0; i < 16; ++i) {
            float4 ww = sW4[i*8 + o4];
            acc.x += a[i]*ww.x; acc.y += a[i]*ww.y; acc.z += a[i]*ww.z; acc.w += a[i]*ww.w;
        }
        acc.x = fmaxf(acc.x, 0.f); acc.y = fmaxf(acc.y, 0.f);
        acc.z = fmaxf(acc.z, 0.f); acc.w = fmaxf(acc.w, 0.f);
        out4[o4] = acc;
        tile[w][lane][o4*4]   = acc.x; tile[w][lane][o4*4+1] = acc.y;
        tile[w][lane][o4*4+2] = acc.z; tile[w][lane][o4*4+3] = acc.w;
    }
    __syncwarp();
    float s = 0.f, ss = 0.f;
    #pragma unroll
    for (int j = 0; j < 32; ++j) {
        float v = tile[w][j][lane];
        s += v; ss += v*v;
    }
    atomicAdd(&rsum[lane], s);
    atomicAdd(&rss[lane], ss);
    __syncthreads();
    if (tid < 32) { atomicAdd(&g_sum2[tid], rsum[tid]); atomicAdd(&g_ss2[tid], rss[tid]); }
}

// ---------------- fc3: in-block BN2 fold + final logits (reads g_a2) ----------------
__global__ void __launch_bounds__(128) fc3_kernel(float* __restrict__ out,
                                                  const float* __restrict__ fc3w,
                                                  const float* __restrict__ fc3b,
                                                  const float* __restrict__ g2,
                                                  const float* __restrict__ bb2)
{
    __shared__ float sS[32], sOff[32], sW[64], sc3[2];
    int tid = threadIdx.x;
    if (tid < 32) {
        float m = g_sum2[tid] * (1.0f/NGRAPH);
        float v = g_ss2[tid] * (1.0f/NGRAPH) - m*m;
        float sc = rsqrtf(v + BN_EPS) * g2[tid];
        sS[tid] = sc; sOff[tid] = bb2[tid] - m*sc;
    }
    __syncthreads();
    if (tid < 64) sW[tid] = sS[tid >> 1] * fc3w[tid];
    if (tid < 2) {
        float c = fc3b[tid];
        #pragma unroll
        for (int r = 0; r < 32; ++r) c += sOff[r]*fc3w[r*2+tid];
        sc3[tid] = c;
    }
    __syncthreads();
    int b = blockIdx.x*128 + tid;
    const float4* a2r = (const float4*)&g_a2[b*32];
    float o0 = sc3[0], o1 = sc3[1];
    #pragma unroll
    for (int q = 0; q < 8; ++q) {
        float4 v = a2r[q];
        o0 += v.x*sW[(q*4+0)*2]   + v.y*sW[(q*4+1)*2]   + v.z*sW[(q*4+2)*2]   + v.w*sW[(q*4+3)*2];
        o1 += v.x*sW[(q*4+0)*2+1] + v.y*sW[(q*4+1)*2+1] + v.z*sW[(q*4+2)*2+1] + v.w*sW[(q*4+3)*2+1];
    }
    ((float2*)out)[b] = make_float2(o0, o1);
}

// ---------------- launch ----------------
extern "C" void kernel_launch(void* const* d_in, const int* in_sizes, int n_in,
                              void* d_out, int out_size)
{
    const float* x    = (const float*)d_in[0];
    const int*   ei   = (const int*)  d_in[1];
    const float* W11  = (const float*)d_in[2];
    const float* b11  = (const float*)d_in[3];
    const float* W21  = (const float*)d_in[4];
    const float* b21  = (const float*)d_in[5];
    const float* W12  = (const float*)d_in[6];
    const float* b12  = (const float*)d_in[7];
    const float* W22  = (const float*)d_in[8];
    const float* b22  = (const float*)d_in[9];
    const float* W13  = (const float*)d_in[10];
    const float* b13  = (const float*)d_in[11];
    const float* W23  = (const float*)d_in[12];
    const float* b23  = (const float*)d_in[13];
    const float* fc1w = (const float*)d_in[14];
    const float* fc1b = (const float*)d_in[15];
    const float* bn1g = (const float*)d_in[16];
    const float* bn1b = (const float*)d_in[17];
    const float* fc2w = (const float*)d_in[18];
    const float* fc2b = (const float*)d_in[19];
    const float* bn2g = (const float*)d_in[20];
    const float* bn2b = (const float*)d_in[21];
    const float* fc3w = (const float*)d_in[22];
    const float* fc3b = (const float*)d_in[23];

    prep_kernel<<<1, 256>>>(W11,b11,W21,b21,W12,b12,W22,b22,W13,b13,W23,b23,fc1w,fc1b);
    gcn_kernel<<<NGRAPH/(WPC*GPW), T1>>>(x, ei);
    fc2_kernel<<<NGRAPH/128, 128>>>(fc2w, fc2b, bn1g, bn1b);
    fc3_kernel<<<NGRAPH/128, 128>>>((float*)d_out, fc3w, fc3b, bn2g, bn2b);
}

// round 12
// speedup vs baseline: 1.0256x; 1.0102x over previous
#include <cuda_runtime.h>

typedef unsigned long long u64;
typedef unsigned int u32;
typedef unsigned short u16;

#define NPG 50
#define EPG 400
#define NGRAPH 32768
#define NEDGE (NGRAPH*EPG)
#define WPC 8                 // warps per CTA in gcn
#define GPW 8                 // graphs per warp
#define T1 (WPC*32)
#define NB 13                 // edge batches of 32 (12*32+16 = 400)
#define PITCH16 56            // u16 cells per tag row (112B: conflict-free LDS.128)
#define BN_EPS 1e-5f

#define FMA2(acc,a,b) asm("fma.rn.f32x2 %0,%1,%2,%0;" : "+l"(acc) : "l"(a), "l"(b))
#define ADD2(acc,a)   asm("add.rn.f32x2 %0,%1,%0;"    : "+l"(acc) : "l"(a))
__device__ __forceinline__ u64 packf2(float lo, float hi) {
    u64 r; asm("mov.b64 %0,{%1,%2};" : "=l"(r) : "r"(__float_as_uint(lo)), "r"(__float_as_uint(hi)));
    return r;
}
__device__ __forceinline__ float lo32(u64 v){ return __uint_as_float((unsigned)v); }
__device__ __forceinline__ float hi32(u64 v){ return __uint_as_float((unsigned)(v>>32)); }

// ---------------- device scratch (static; no allocation) ----------------
__device__ u64   g_GGc[NPG*16];    // interleaved (G, Gc) folded fc1 weights
__device__ float g_e1[16];
__device__ float g_sum1[16], g_ss1[16];
__device__ float g_sum2[32], g_ss2[32];
__device__ float g_a1[NGRAPH*16];  // 2 MB
__device__ float g_a2[NGRAPH*32];  // 4 MB

// ---------------- prep: fold W1k@W2k into fc1, zero accumulators ----------------
__global__ void prep_kernel(const float* __restrict__ W11, const float* __restrict__ b11,
                            const float* __restrict__ W21, const float* __restrict__ b21,
                            const float* __restrict__ W12, const float* __restrict__ b12,
                            const float* __restrict__ W22, const float* __restrict__ b22,
                            const float* __restrict__ W13, const float* __restrict__ b13,
                            const float* __restrict__ W23, const float* __restrict__ b23,
                            const float* __restrict__ fc1w, const float* __restrict__ fc1b)
{
    __shared__ float u[12], cv[12], dv[12];
    int tid = threadIdx.x;
    if (tid < 12) {
        int k = tid / 4, o = tid % 4;
        const float* W1 = (k==0) ? W11 : ((k==1) ? W12 : W13);
        const float* W2 = (k==0) ? W21 : ((k==1) ? W22 : W23);
        const float* b1 = (k==0) ? b11 : ((k==1) ? b12 : b13);
        const float* b2 = (k==0) ? b21 : ((k==1) ? b22 : b23);
        float uu = 0.f, cc = 0.f;
        #pragma unroll
        for (int m = 0; m < 4; ++m) { uu += W1[m]*W2[m*4+o]; cc += b1[m]*W2[m*4+o]; }
        u[tid] = uu; cv[tid] = cc; dv[tid] = b2[o];
    }
    __syncthreads();
    for (int i = tid; i < NPG*16; i += blockDim.x) {
        int j = i >> 4, o = i & 15;
        float gg = 0.f, gc = 0.f;
        #pragma unroll
        for (int f = 0; f < 12; ++f) {
            float w = fc1w[(j*12+f)*16 + o];
            gg += u[f]*w; gc += cv[f]*w;
        }
        g_GGc[i] = packf2(gg, gc);
    }
    if (tid < 16) {
        float e = fc1b[tid];
        for (int j = 0; j < NPG; ++j)
            #pragma unroll
            for (int f = 0; f < 12; ++f)
                e += dv[f]*fc1w[(j*12+f)*16 + tid];
        g_e1[tid] = e;
        g_sum1[tid] = 0.f; g_ss1[tid] = 0.f;
    }
    if (tid < 32) { g_sum2[tid] = 0.f; g_ss2[tid] = 0.f; }
}

// ---- scan one tag row -> 50-bit structure mask (m0: cells 0..31, m1: 32..49) ----
// cell valid iff tag epoch byte matches: ((tag>>8) ^ (gi<<1)) & 0xFE == 0
__device__ __forceinline__ void scan_row_tags(const u16* __restrict__ tag, int r, u32 ep2,
                                              u32& m0, u32& m1)
{
    const uint4* row4 = (const uint4*)(tag + r*PITCH16);
    m0 = 0; m1 = 0;
    #pragma unroll
    for (int k4 = 0; k4 < 7; ++k4) {
        uint4 q = row4[k4];
        u32 p0 = __byte_perm(q.x, q.y, 0x7531);    // hi-bytes of 4 u16 cells
        u32 p1 = __byte_perm(q.z, q.w, 0x7531);
        u32 v0 = (p0 ^ ep2) & 0xFEFEFEFEu;
        u32 v1 = (p1 ^ ep2) & 0xFEFEFEFEu;
        u32 f0 = __vseteq4(v0, 0u);                // 0x01 per valid cell
        u32 f1 = __vseteq4(v1, 0u);
        u32 nib = ((f0 * 0x01020408u) >> 24) | ((((f1 * 0x01020408u) >> 24)) << 4);
        if (k4 < 4) m0 |= nib << (8*k4); else m1 |= nib << (8*(k4-4));
    }
}

// ---- packed sweep: ident + structure bits + dup bits (each dup cell counted twice total) ----
__device__ __forceinline__ u64 sweep1p(u32 m0, u32 m1, u32 dl, u32 dh,
                                       const u64* __restrict__ wv, u64 acc)
{
    while (m0) { int j = __ffs(m0)-1;  m0 &= m0-1; u64 v = wv[j]; ADD2(acc, v); }
    while (m1) { int j = __ffs(m1)+31; m1 &= m1-1; u64 v = wv[j]; ADD2(acc, v); }
    while (dl) { int j = __ffs(dl)-1;  dl &= dl-1; u64 v = wv[j]; ADD2(acc, v); }
    while (dh) { int j = __ffs(dh)+31; dh &= dh-1; u64 v = wv[j]; ADD2(acc, v); }
    return acc;
}
__device__ __forceinline__ float sweep2s(u32 m0, u32 m1, u32 dl, u32 dh,
                                         const float* __restrict__ wv, float acc)
{
    while (m0) { int j = __ffs(m0)-1;  m0 &= m0-1; acc += wv[j]; }
    while (m1) { int j = __ffs(m1)+31; m1 &= m1-1; acc += wv[j]; }
    while (dl) { int j = __ffs(dl)-1;  dl &= dl-1; acc += wv[j]; }
    while (dh) { int j = __ffs(dh)+31; dh &= dh-1; acc += wv[j]; }
    return acc;
}

// ---------------- main GCN kernel: warp-per-graph, tag-dedup build (STS not atomics) ----------------
__global__ void __launch_bounds__(T1, 3) gcn_kernel(const float* __restrict__ x,
                                                    const int* __restrict__ ei)
{
    __shared__ __align__(16) u16 sTag[WPC][NPG*PITCH16];  // 5.6KB/warp last-writer tags
    __shared__ u64   sWxd[WPC][NPG];
    __shared__ float sW2[WPC][NPG];
    __shared__ u64   sYR[WPC][NPG];
    __shared__ u64   sDm[WPC][NPG];                        // dup masks (count>=2 cells)
    __shared__ u16   sTrl[WPC][64];                        // triple+ list (rare)
    __shared__ int   sNtr[WPC];
    __shared__ u64   sGGc[NPG*16];
    __shared__ float se1[16];

    int tid = threadIdx.x, w = tid >> 5, lane = tid & 31;
    // once per launch: invalidate all tags (0xFFFF never matches any epoch)
    {
        u32* tp = (u32*)sTag;
        for (int i = tid; i < WPC*NPG*PITCH16/2; i += T1) tp[i] = 0xFFFFFFFFu;
    }
    for (int i = tid; i < NPG*16; i += T1) sGGc[i] = g_GGc[i];
    if (tid < 16) se1[tid] = g_e1[tid];
    __syncthreads();

    u16*  tag = sTag[w];
    u64*  wxd = sWxd[w];
    float* w2 = sW2[w];
    u64*  yr  = sYR[w];
    u64*  dm  = sDm[w];
    u16*  trl = sTrl[w];

    const int r1 = lane, r2 = 32 + lane;
    const bool has2 = (lane < NPG - 32);
    float psum = 0.f, pss = 0.f;
    int gbase = (blockIdx.x * WPC + w) * GPW;

    int eS[NB], eD[NB]; float px1, px2;
    {   // prologue: first graph's edges + x
        int eb = gbase*EPG, nb0 = gbase*NPG;
        #pragma unroll
        for (int b = 0; b < NB; ++b) {
            bool act = (b < 12) || (lane < 16);
            int e = lane + b*32;
            eS[b] = act ? ei[eb+e] : nb0;
            eD[b] = act ? ei[NEDGE+eb+e] : nb0;
        }
        px1 = x[nb0 + r1];
        px2 = has2 ? x[nb0 + r2] : 0.f;
    }

    for (int gi = 0; gi < GPW; ++gi) {
        int g = gbase + gi, nb = g*NPG;
        float x1 = px1, x2 = px2;
        // Z: zero dup masks + triple count
        dm[r1] = 0ull;
        if (has2) dm[r2] = 0ull;
        if (lane == 0) sNtr[w] = 0;
        __syncwarp();
        // T: last-writer tag write (plain STS; races pick one winner)
        u32 epv = (u32)gi << 9;
        #pragma unroll
        for (int b = 0; b < NB; ++b) {
            bool act = (b < 12) || (lane < 16);
            if (act) {
                int s = eS[b]-nb, d = eD[b]-nb;
                tag[d*PITCH16 + s] = (u16)(epv | (u32)(b*32 + lane));
            }
        }
        __syncwarp();
        // R: read back -> non-owners are duplicates; set dup-mask bit; triples to list
        #pragma unroll
        for (int b = 0; b < NB; ++b) {
            bool act = (b < 12) || (lane < 16);
            if (act) {
                int s = eS[b]-nb, d = eD[b]-nb;
                u16 t = tag[d*PITCH16 + s];
                if (t != (u16)(epv | (u32)(b*32 + lane))) {
                    u64 bit = 1ull << s;
                    u64 old = atomicOr(&dm[d], bit);
                    if (old & bit) {
                        int k = atomicAdd(&sNtr[w], 1);
                        if (k < 64) trl[k] = (u16)(d*64 + s);
                    }
                }
            }
        }
        // prefetch next graph's edges + x
        if (gi + 1 < GPW) {
            int eb2 = (g+1)*EPG, nb2 = (g+1)*NPG;
            #pragma unroll
            for (int b = 0; b < NB; ++b) {
                bool act = (b < 12) || (lane < 16);
                int e = lane + b*32;
                if (act) { eS[b] = ei[eb2+e]; eD[b] = ei[NEDGE+eb2+e]; }
                else     { eS[b] = nb2; eD[b] = nb2; }
            }
            px1 = x[nb2 + r1];
            px2 = has2 ? x[nb2 + r2] : 0.f;
        }
        __syncwarp();
        // S: scan tags -> register structure masks; degree; wxd
        int ntr = sNtr[w];
        u64 dv1 = dm[r1], dv2 = has2 ? dm[r2] : 0ull;
        u32 ep2 = ((u32)gi << 1) * 0x01010101u;
        u32 m0a, m1a, m0b = 0, m1b = 0;
        scan_row_tags(tag, r1, ep2, m0a, m1a);
        if (has2) scan_row_tags(tag, r2, ep2, m0b, m1b);
        float degA = 1.f + (float)(__popc(m0a) + __popc(m1a) + __popcll(dv1));
        float degB = 1.f + (float)(__popc(m0b) + __popc(m1b) + __popcll(dv2));
        if (ntr) {
            for (int k = 0; k < ntr && k < 64; ++k) {
                int c = trl[k], d = c >> 6;
                if (d == r1) degA += 1.f;
                if (has2 && d == r2) degB += 1.f;
            }
        }
        float di1 = rsqrtf(degA), di2 = rsqrtf(degB);
        u64 idA = packf2(x1*di1, di1);
        wxd[r1] = idA;
        u64 idB = 0;
        if (has2) { idB = packf2(x2*di2, di2); wxd[r2] = idB; }
        __syncwarp();
        // sweep 1 (x-path + ones-path packed f32x2)
        u64 acca = sweep1p(m0a, m1a, (u32)dv1, (u32)(dv1>>32), wxd, idA);
        u64 accb = has2 ? sweep1p(m0b, m1b, (u32)dv2, (u32)(dv2>>32), wxd, idB) : 0ull;
        if (ntr) {
            for (int k = 0; k < ntr && k < 64; ++k) {
                int c = trl[k], d = c >> 6, s = c & 63;
                if (d == r1)          { u64 v = wxd[s]; ADD2(acca, v); }
                if (has2 && d == r2)  { u64 v = wxd[s]; ADD2(accb, v); }
            }
        }
        float rv1 = hi32(acca)*di1;
        float w2a = lo32(acca)*di1*di1;
        w2[r1] = w2a;
        float rv2 = 0.f, w2b = 0.f;
        if (has2) { rv2 = hi32(accb)*di2; w2b = lo32(accb)*di2*di2; w2[r2] = w2b; }
        __syncwarp();
        // sweep 2 (scalar)
        float a2v = sweep2s(m0a, m1a, (u32)dv1, (u32)(dv1>>32), w2, w2a);
        float b2v = has2 ? sweep2s(m0b, m1b, (u32)dv2, (u32)(dv2>>32), w2, w2b) : 0.f;
        if (ntr) {
            for (int k = 0; k < ntr && k < 64; ++k) {
                int c = trl[k], d = c >> 6, s = c & 63;
                if (d == r1)         a2v += w2[s];
                if (has2 && d == r2) b2v += w2[s];
            }
        }
        yr[r1] = packf2(a2v*di1, rv1);
        if (has2) yr[r2] = packf2(b2v*di2, rv2);
        __syncwarp();
        // fc1: a1[g,o] = e1[o] + sum_j yv[j]G[j,o] + rv[j]Gc[j,o]
        {
            int o = lane & 15, half = lane >> 4;
            int j0 = half * 25;
            u64 acc = 0;
            #pragma unroll
            for (int j = 0; j < 25; ++j) {
                u64 y  = yr[j0 + j];
                u64 gg = sGGc[(j0 + j)*16 + o];
                FMA2(acc, y, gg);
            }
            float s = lo32(acc) + hi32(acc);
            s += __shfl_down_sync(0xffffffffu, s, 16);
            if (lane < 16) {
                float a = fmaxf(se1[o] + s, 0.f);
                g_a1[g*16 + o] = a;
                psum += a; pss += a*a;
            }
        }
        __syncwarp();
    }
    if (lane < 16) { atomicAdd(&g_sum1[lane], psum); atomicAdd(&g_ss1[lane], pss); }
}

// ---------------- fc2: BN1 fold + GEMV + relu -> g_a2 + BN2 stats (transpose tile) ----------------
__global__ void __launch_bounds__(128) fc2_kernel(const float* __restrict__ fc2w,
                                                  const float* __restrict__ fc2b,
                                                  const float* __restrict__ g1,
                                                  const float* __restrict__ bb1)
{
    __shared__ float sS[16], sOff[16];
    __shared__ float4 sW4[16*8];
    __shared__ float sc2[32];
    __shared__ float tile[4][32][33];
    __shared__ float rsum[32], rss[32];
    int tid = threadIdx.x, lane = tid & 31, w = tid >> 5;
    if (tid < 16) {
        float m = g_sum1[tid] * (1.0f/NGRAPH);
        float v = g_ss1[tid] * (1.0f/NGRAPH) - m*m;
        float sc = rsqrtf(v + BN_EPS) * g1[tid];
        sS[tid] = sc; sOff[tid] = bb1[tid] - m*sc;
    }
    if (tid < 32) { rsum[tid] = 0.f; rss[tid] = 0.f; }
    __syncthreads();
    float* sW = (float*)sW4;
    for (int i = tid; i < 512; i += 128) sW[i] = sS[i >> 5] * fc2w[i];
    if (tid < 32) {
        float c = fc2b[tid];
        #pragma unroll
        for (int r = 0; r < 16; ++r) c += sOff[r]*fc2w[r*32+tid];
        sc2[tid] = c;
    }
    __syncthreads();

    int b = blockIdx.x*128 + tid;
    const float4* a4 = (const float4*)&g_a1[b*16];
    float4 r0 = a4[0], r1 = a4[1], r2 = a4[2], r3 = a4[3];
    float a[16] = {r0.x,r0.y,r0.z,r0.w, r1.x,r1.y,r1.z,r1.w,
                   r2.x,r2.y,r2.z,r2.w, r3.x,r3.y,r3.z,r3.w};
    float4* out4 = (float4*)&g_a2[b*32];
    #pragma unroll
    for (int o4 = 0; o4 < 8; ++o4) {
        float4 acc = make_float4(sc2[o4*4], sc2[o4*4+1], sc2[o4*4+2], sc2[o4*4+3]);
        #pragma unroll
        for (int i = 0; i < 16; ++i) {
            float4 ww = sW4[i*8 + o4];
            acc.x += a[i]*ww.x; acc.y += a[i]*ww.y; acc.z += a[i]*ww.z; acc.w += a[i]*ww.w;
        }
        acc.x = fmaxf(acc.x, 0.f); acc.y = fmaxf(acc.y, 0.f);
        acc.z = fmaxf(acc.z, 0.f); acc.w = fmaxf(acc.w, 0.f);
        out4[o4] = acc;
        tile[w][lane][o4*4]   = acc.x; tile[w][lane][o4*4+1] = acc.y;
        tile[w][lane][o4*4+2] = acc.z; tile[w][lane][o4*4+3] = acc.w;
    }
    __syncwarp();
    float s = 0.f, ss = 0.f;
    #pragma unroll
    for (int j = 0; j < 32; ++j) {
        float v = tile[w][j][lane];
        s += v; ss += v*v;
    }
    atomicAdd(&rsum[lane], s);
    atomicAdd(&rss[lane], ss);
    __syncthreads();
    if (tid < 32) { atomicAdd(&g_sum2[tid], rsum[tid]); atomicAdd(&g_ss2[tid], rss[tid]); }
}

// ---------------- fc3: in-block BN2 fold + final logits (reads g_a2) ----------------
__global__ void __launch_bounds__(128) fc3_kernel(float* __restrict__ out,
                                                  const float* __restrict__ fc3w,
                                                  const float* __restrict__ fc3b,
                                                  const float* __restrict__ g2,
                                                  const float* __restrict__ bb2)
{
    __shared__ float sS[32], sOff[32], sW[64], sc3[2];
    int tid = threadIdx.x;
    if (tid < 32) {
        float m = g_sum2[tid] * (1.0f/NGRAPH);
        float v = g_ss2[tid] * (1.0f/NGRAPH) - m*m;
        float sc = rsqrtf(v + BN_EPS) * g2[tid];
        sS[tid] = sc; sOff[tid] = bb2[tid] - m*sc;
    }
    __syncthreads();
    if (tid < 64) sW[tid] = sS[tid >> 1] * fc3w[tid];
    if (tid < 2) {
        float c = fc3b[tid];
        #pragma unroll
        for (int r = 0; r < 32; ++r) c += sOff[r]*fc3w[r*2+tid];
        sc3[tid] = c;
    }
    __syncthreads();
    int b = blockIdx.x*128 + tid;
    const float4* a2r = (const float4*)&g_a2[b*32];
    float o0 = sc3[0], o1 = sc3[1];
    #pragma unroll
    for (int q = 0; q < 8; ++q) {
        float4 v = a2r[q];
        o0 += v.x*sW[(q*4+0)*2]   + v.y*sW[(q*4+1)*2]   + v.z*sW[(q*4+2)*2]   + v.w*sW[(q*4+3)*2];
        o1 += v.x*sW[(q*4+0)*2+1] + v.y*sW[(q*4+1)*2+1] + v.z*sW[(q*4+2)*2+1] + v.w*sW[(q*4+3)*2+1];
    }
    ((float2*)out)[b] = make_float2(o0, o1);
}

// ---------------- launch ----------------
extern "C" void kernel_launch(void* const* d_in, const int* in_sizes, int n_in,
                              void* d_out, int out_size)
{
    const float* x    = (const float*)d_in[0];
    const int*   ei   = (const int*)  d_in[1];
    const float* W11  = (const float*)d_in[2];
    const float* b11  = (const float*)d_in[3];
    const float* W21  = (const float*)d_in[4];
    const float* b21  = (const float*)d_in[5];
    const float* W12  = (const float*)d_in[6];
    const float* b12  = (const float*)d_in[7];
    const float* W22  = (const float*)d_in[8];
    const float* b22  = (const float*)d_in[9];
    const float* W13  = (const float*)d_in[10];
    const float* b13  = (const float*)d_in[11];
    const float* W23  = (const float*)d_in[12];
    const float* b23  = (const float*)d_in[13];
    const float* fc1w = (const float*)d_in[14];
    const float* fc1b = (const float*)d_in[15];
    const float* bn1g = (const float*)d_in[16];
    const float* bn1b = (const float*)d_in[17];
    const float* fc2w = (const float*)d_in[18];
    const float* fc2b = (const float*)d_in[19];
    const float* bn2g = (const float*)d_in[20];
    const float* bn2b = (const float*)d_in[21];
    const float* fc3w = (const float*)d_in[22];
    const float* fc3b = (const float*)d_in[23];

    prep_kernel<<<1, 256>>>(W11,b11,W21,b21,W12,b12,W22,b22,W13,b13,W23,b23,fc1w,fc1b);
    gcn_kernel<<<NGRAPH/(WPC*GPW), T1>>>(x, ei);
    fc2_kernel<<<NGRAPH/128, 128>>>(fc2w, fc2b, bn1g, bn1b);
    fc3_kernel<<<NGRAPH/128, 128>>>((float*)d_out, fc3w, fc3b, bn2g, bn2b);
}